// round 2
// baseline (speedup 1.0000x reference)
#include <cuda_runtime.h>
#include <cstdint>

// ---------------------------------------------------------------------------
// Wav2Vec2 Gumbel VQ (inference path):
//   logits = h @ W + b           h:[BT=65536, 512]  W:[512, 640]
//   idx    = argmax per (token, group of 320)
//   out[t] = concat(cb[0, idx0], cb[1, idx1])   (256 floats per token)
//   perplexity scalar from the count histogram  -> d_out[out_size-1]
// ---------------------------------------------------------------------------

namespace {
constexpr int kBT      = 65536;   // B*S tokens
constexpr int kH       = 512;     // hidden dim (K of GEMM)
constexpr int kGV      = 640;     // G*V logits per token
constexpr int kV       = 320;     // codes per group
constexpr int kBM      = 64;      // tokens per CTA
constexpr int kThreads = 256;
constexpr int kNC      = 32;      // logit columns per chunk
constexpr int kNChunks = kGV / kNC;          // 20 (0..9 group0, 10..19 group1)
constexpr int kHS      = kH + 4;  // smem row stride (floats) for h  (516)
constexpr int kWS      = kH + 4;  // smem row stride (floats) for w^T (516)
constexpr int kSmemBytes = (kBM * kHS + kNC * kWS) * 4;   // 198144 B
}  // namespace

__device__ int g_counts[kGV];

// packed f32x2 FMA: acc.{lo,hi} += a.{lo,hi} * b.{lo,hi}
__device__ __forceinline__ void fma2(unsigned long long& acc,
                                     unsigned long long a,
                                     unsigned long long b) {
    asm("fma.rn.f32x2 %0, %1, %2, %0;" : "+l"(acc) : "l"(a), "l"(b));
}

__device__ __forceinline__ float pairsum(unsigned long long a) {
    float lo = __uint_as_float((unsigned int)a);
    float hi = __uint_as_float((unsigned int)(a >> 32));
    return lo + hi;
}

__global__ void __launch_bounds__(kThreads, 1)
vq_main(const float* __restrict__ hid,   // [BT, 512]
        const float* __restrict__ W,     // [512, 640]
        const float* __restrict__ bias,  // [640]
        const float* __restrict__ cb,    // [640, 128]
        float* __restrict__ out)         // [BT, 256]
{
    extern __shared__ float smem[];
    float* h_s = smem;                 // [kBM][kHS]
    float* w_s = smem + kBM * kHS;     // [kNC][kWS]  (W chunk, transposed)

    const int tid = threadIdx.x;
    const int m0  = blockIdx.x * kBM;

    // ---- load h tile (64 x 512 fp32, coalesced float4) ----
    {
        const float4* hg = (const float4*)(hid + (size_t)m0 * kH);
        for (int e = tid; e < kBM * (kH / 4); e += kThreads) {
            int m  = e >> 7;        // /128
            int k4 = e & 127;
            float4 v = hg[(size_t)m * (kH / 4) + k4];
            *(float4*)(h_s + m * kHS + k4 * 4) = v;
        }
    }

    const int tn = tid & 15;           // 16 n-threads (2 cols each)
    const int tm = tid >> 4;           // 16 m-threads (4 rows each)
    const int mb = tm * 4;

    const int lane   = tid & 31;
    const int warp   = tid >> 5;
    const int nlo    = lane & 7;       // W-chunk loader mapping
    const int kq_off = lane >> 3;

    float bmax[4], g0max[4];
    int   bidx[4], g0idx[4];
#pragma unroll
    for (int i = 0; i < 4; i++) { bmax[i] = -3.4e38f; bidx[i] = 0;
                                  g0max[i] = -3.4e38f; g0idx[i] = 0; }

    const ulonglong2* hu[4];
#pragma unroll
    for (int i = 0; i < 4; i++)
        hu[i] = (const ulonglong2*)(h_s + (mb + i) * kHS);

    for (int c = 0; c < kNChunks; c++) {
        const int n0 = c * kNC;

        // ---- stage W[:, n0:n0+32] transposed into w_s[n][k] ----
        // per-warp: 8 n-values x 4 k-values -> conflict-free STS, 4x32B LDG
#pragma unroll 4
        for (int j = 0; j < 64; j++) {
            int q    = warp + (j << 3);     // 0..511
            int nhi  = q & 3;
            int kblk = q >> 2;              // 0..127
            int k    = (kblk << 2) + kq_off;
            int nl   = (nhi << 3) + nlo;
            w_s[nl * kWS + k] = W[(size_t)k * kGV + (n0 + nl)];
        }
        __syncthreads();

        // ---- 64x32x512 fp32 GEMM chunk via packed f32x2 FMA ----
        unsigned long long acc[4][2];
#pragma unroll
        for (int i = 0; i < 4; i++) { acc[i][0] = 0ull; acc[i][1] = 0ull; }

        const ulonglong2* wu0 = (const ulonglong2*)(w_s + (2 * tn) * kWS);
        const ulonglong2* wu1 = (const ulonglong2*)(w_s + (2 * tn + 1) * kWS);

#pragma unroll 4
        for (int kk = 0; kk < kH / 4; kk++) {
            ulonglong2 w0 = wu0[kk];
            ulonglong2 w1 = wu1[kk];
#pragma unroll
            for (int i = 0; i < 4; i++) {
                ulonglong2 h = hu[i][kk];
                fma2(acc[i][0], h.x, w0.x);
                fma2(acc[i][0], h.y, w0.y);
                fma2(acc[i][1], h.x, w1.x);
                fma2(acc[i][1], h.y, w1.y);
            }
        }

        // ---- fold + running argmax ----
        const float b0 = bias[n0 + 2 * tn];
        const float b1 = bias[n0 + 2 * tn + 1];
        const int   nbase = n0 + 2 * tn - ((c >= 10) ? kV : 0);
#pragma unroll
        for (int i = 0; i < 4; i++) {
            float v0 = pairsum(acc[i][0]) + b0;
            float v1 = pairsum(acc[i][1]) + b1;
            if (v0 > bmax[i]) { bmax[i] = v0; bidx[i] = nbase; }
            if (v1 > bmax[i]) { bmax[i] = v1; bidx[i] = nbase + 1; }
        }
        if (c == 9) {
#pragma unroll
            for (int i = 0; i < 4; i++) {
                g0max[i] = bmax[i]; g0idx[i] = bidx[i];
                bmax[i] = -3.4e38f; bidx[i] = 0;
            }
        }
        __syncthreads();   // w_s rewritten next chunk
    }

    // ---- cross-thread argmax reduction (reuse w_s as scratch) ----
    float* rmax  = w_s;                       // [2][64][16] floats
    int*   ridx  = (int*)(w_s + 2048);        // [2][64][16] ints
    int*   idx_s = (int*)(w_s + 4096);        // [64][2] ints
#pragma unroll
    for (int i = 0; i < 4; i++) {
        int m = mb + i;
        rmax[m * 16 + tn]        = g0max[i];
        ridx[m * 16 + tn]        = g0idx[i];
        rmax[1024 + m * 16 + tn] = bmax[i];
        ridx[1024 + m * 16 + tn] = bidx[i];
    }
    __syncthreads();

    if (tid < 128) {
        int g = tid >> 6;
        int m = tid & 63;
        int base = g * 1024 + m * 16;
        float best = -3.4e38f; int bi = 0x7fffffff;
#pragma unroll
        for (int t = 0; t < 16; t++) {
            float v = rmax[base + t];
            int   id = ridx[base + t];
            if (v > best || (v == best && id < bi)) { best = v; bi = id; }
        }
        atomicAdd(&g_counts[g * kV + bi], 1);
        idx_s[(m << 1) | g] = bi;
    }
    __syncthreads();

    // ---- gather codevectors, coalesced float4 writes ----
    const float4* cbv  = (const float4*)cb;   // 640 rows x 32 float4
    float4*       outv = (float4*)out;
    for (int e = tid; e < kBM * 64; e += kThreads) {
        int m = e >> 6;
        int q = e & 63;            // 0..63 float4 within the 256-float row
        int g = q >> 5;
        int j = q & 31;
        int vi = idx_s[(m << 1) | g];
        outv[(size_t)(m0 + m) * 64 + q] = cbv[(size_t)(g * kV + vi) * 32 + j];
    }
}

__global__ void vq_zero() {
    if (threadIdx.x < kGV) g_counts[threadIdx.x] = 0;
}

__global__ void vq_ppl(float* __restrict__ out, int out_size) {
    __shared__ float terms[2 * kV];
    int t = threadIdx.x;               // 320 threads
    for (int g = 0; g < 2; g++) {
        float m = (float)g_counts[g * kV + t] / (float)kBT;
        terms[g * kV + t] = m * logf(m + 1e-7f);
    }
    __syncthreads();
    if (t == 0) {
        float p = 0.f;
        for (int g = 0; g < 2; g++) {
            float s = 0.f;
            for (int v = 0; v < kV; v++) s += terms[g * kV + v];
            p += expf(-s);
        }
        out[out_size - 1] = p;
    }
}

extern "C" void kernel_launch(void* const* d_in, const int* in_sizes, int n_in,
                              void* d_out, int out_size) {
    (void)in_sizes; (void)n_in;
    const float* hid  = (const float*)d_in[0];
    const float* W    = (const float*)d_in[1];
    const float* bias = (const float*)d_in[2];
    const float* cb   = (const float*)d_in[3];
    float* out = (float*)d_out;

    cudaFuncSetAttribute(vq_main, cudaFuncAttributeMaxDynamicSharedMemorySize,
                         kSmemBytes);

    vq_zero<<<1, kGV>>>();
    vq_main<<<kBT / kBM, kThreads, kSmemBytes>>>(hid, W, bias, cb, out);
    vq_ppl<<<1, kV>>>(out, out_size);
}

// round 4
// speedup vs baseline: 2.6470x; 2.6470x over previous
#include <cuda_runtime.h>
#include <cuda_bf16.h>
#include <cstdint>

// ---------------------------------------------------------------------------
// Wav2Vec2 Gumbel VQ via legacy tensor cores (mma.sync bf16, sm_100 baseline).
//   logits = h @ W + b with bf16x3 split, 6 products (fp32-quality).
//   argmax per (token, group) -> codevector gather + perplexity.
// ---------------------------------------------------------------------------

namespace {
constexpr int kBT = 65536;
constexpr int kH  = 512;
constexpr int kV  = 320;
constexpr int kG  = 2;
constexpr int kGV = kG * kV;

constexpr int kMT = 64;                   // tokens per CTA
constexpr int kKC = 32;                   // K per chunk (2 mma k-steps)
constexpr int kChunks = kH / kKC;         // 16

constexpr uint32_t kRowB   = 80;                           // padded row bytes (32 bf16 -> 80B)
constexpr uint32_t kAterm  = kMT * kRowB;                  // 5120
constexpr uint32_t kBterm  = kV * kRowB;                   // 25600
constexpr uint32_t kStage  = 3 * kAterm + 3 * kBterm;      // 92160
constexpr uint32_t kHdr    = 4096;
constexpr uint32_t kSmemBytes = kHdr + 2 * kStage;         // 188416
}  // namespace

// global scratch (no cudaMalloc allowed)
__device__ __align__(256) __nv_bfloat16 g_h1[(size_t)kBT * kH];
__device__ __align__(256) __nv_bfloat16 g_h2[(size_t)kBT * kH];
__device__ __align__(256) __nv_bfloat16 g_h3[(size_t)kBT * kH];
__device__ __align__(256) __nv_bfloat16 g_w1t[kGV * kH];
__device__ __align__(256) __nv_bfloat16 g_w2t[kGV * kH];
__device__ __align__(256) __nv_bfloat16 g_w3t[kGV * kH];
__device__ int g_counts[kGV];

// ---------------- PTX helpers ----------------
__device__ __forceinline__ uint32_t smem_u32(const void* p) {
    uint32_t a;
    asm("{ .reg .u64 t; cvta.to.shared.u64 t, %1; cvt.u32.u64 %0, t; }"
        : "=r"(a) : "l"(p));
    return a;
}
__device__ __forceinline__ void cpa16(uint32_t s, const void* g) {
    asm volatile("cp.async.cg.shared.global [%0], [%1], 16;" :: "r"(s), "l"(g));
}
__device__ __forceinline__ void cpa_commit() {
    asm volatile("cp.async.commit_group;" ::: "memory");
}
__device__ __forceinline__ void ldsm4(uint32_t* d, uint32_t addr) {
    asm volatile("ldmatrix.sync.aligned.m8n8.x4.shared.b16 {%0,%1,%2,%3}, [%4];"
                 : "=r"(d[0]), "=r"(d[1]), "=r"(d[2]), "=r"(d[3]) : "r"(addr));
}
__device__ __forceinline__ void mma16816(float* c, const uint32_t* a,
                                         uint32_t b0, uint32_t b1) {
    asm volatile(
        "mma.sync.aligned.m16n8k16.row.col.f32.bf16.bf16.f32 "
        "{%0,%1,%2,%3}, {%4,%5,%6,%7}, {%8,%9}, {%0,%1,%2,%3};"
        : "+f"(c[0]), "+f"(c[1]), "+f"(c[2]), "+f"(c[3])
        : "r"(a[0]), "r"(a[1]), "r"(a[2]), "r"(a[3]), "r"(b0), "r"(b1));
}

// ---------------- split kernels ----------------
__device__ __forceinline__ uint32_t pk2(__nv_bfloat16 x, __nv_bfloat16 y) {
    return (uint32_t)__bfloat16_as_ushort(x) |
           ((uint32_t)__bfloat16_as_ushort(y) << 16);
}

__global__ void __launch_bounds__(256) split_h_kernel(const float* __restrict__ h) {
    size_t i = (size_t)blockIdx.x * 256 + threadIdx.x;   // one float4 each
    float4 x = ((const float4*)h)[i];
    float v[4] = {x.x, x.y, x.z, x.w};
    __nv_bfloat16 a[4], b[4], c[4];
#pragma unroll
    for (int j = 0; j < 4; j++) {
        a[j] = __float2bfloat16_rn(v[j]);
        float r = v[j] - __bfloat162float(a[j]);
        b[j] = __float2bfloat16_rn(r);
        float r2 = r - __bfloat162float(b[j]);
        c[j] = __float2bfloat16_rn(r2);
    }
    ((uint2*)g_h1)[i] = make_uint2(pk2(a[0], a[1]), pk2(a[2], a[3]));
    ((uint2*)g_h2)[i] = make_uint2(pk2(b[0], b[1]), pk2(b[2], b[3]));
    ((uint2*)g_h3)[i] = make_uint2(pk2(c[0], c[1]), pk2(c[2], c[3]));
}

__global__ void __launch_bounds__(256) split_w_kernel(const float* __restrict__ W) {
    int idx = blockIdx.x * 256 + threadIdx.x;   // over 512*640
    int k = idx / kGV;
    int n = idx - k * kGV;
    float v = W[idx];
    __nv_bfloat16 a = __float2bfloat16_rn(v);
    float r = v - __bfloat162float(a);
    __nv_bfloat16 b = __float2bfloat16_rn(r);
    float r2 = r - __bfloat162float(b);
    __nv_bfloat16 c = __float2bfloat16_rn(r2);
    size_t o = (size_t)n * kH + k;               // transposed [n][k]
    g_w1t[o] = a; g_w2t[o] = b; g_w3t[o] = c;
}

// ---------------- main tensor kernel ----------------
__device__ __forceinline__ void load_chunk(int c, uint32_t Ts, int m0, int g,
                                           int tid) {
    // A: 3 terms x 64 rows x 64B  (4 x 16B per row) -> 768 cp.async
#pragma unroll
    for (int t = 0; t < 3; ++t) {
        int row = tid >> 2, cs = tid & 3;
        const __nv_bfloat16* hp = (t == 0) ? g_h1 : (t == 1) ? g_h2 : g_h3;
        const void* gp = hp + ((size_t)(m0 + row) * kH + c * kKC + cs * 8);
        cpa16(Ts + t * kAterm + row * kRowB + cs * 16, gp);
    }
    // B: 3 terms x 320 rows x 64B -> 3840 cp.async (15 per thread)
    const uint32_t B0 = Ts + 3 * kAterm;
#pragma unroll
    for (int i = 0; i < 15; ++i) {
        int gi = tid + i * 256;
        int t = gi / 1280;
        int e = gi - t * 1280;
        int n = e >> 2, cs = e & 3;
        const __nv_bfloat16* wp = (t == 0) ? g_w1t : (t == 1) ? g_w2t : g_w3t;
        const void* gp = wp + ((size_t)(g * kV + n) * kH + c * kKC + cs * 8);
        cpa16(B0 + t * kBterm + n * kRowB + cs * 16, gp);
    }
    cpa_commit();
}

__global__ void __launch_bounds__(256, 1)
vq_mma(const float* __restrict__ bias,
       const float* __restrict__ cb,      // [640][128]
       float* __restrict__ out)           // [BT][256]
{
    extern __shared__ __align__(1024) char smem_raw[];
    const uint32_t sbase = smem_u32(smem_raw);
    float* red_val = (float*)smem_raw;                 // [64][4]
    int*   red_idx = (int*)(smem_raw + 1024);          // [64][4]
    int*   idx_s   = (int*)(smem_raw + 2048);          // [64]
    float* bias_s  = (float*)(smem_raw + 2304);        // [320]

    const int tid  = threadIdx.x;
    const int warp = tid >> 5;
    const int lane = tid & 31;
    const int mw   = warp >> 2;            // 0..1
    const int nw   = warp & 3;             // 0..3
    const int gID  = lane >> 2;
    const int tig  = lane & 3;
    const int g    = blockIdx.x & 1;
    const int m0   = (blockIdx.x >> 1) * kMT;

    for (int i = tid; i < kV; i += 256) bias_s[i] = bias[g * kV + i];

    load_chunk(0, sbase + kHdr, m0, g, tid);
    load_chunk(1, sbase + kHdr + kStage, m0, g, tid);

    float acc[2][10][4];
#pragma unroll
    for (int mf = 0; mf < 2; ++mf)
#pragma unroll
        for (int nf = 0; nf < 10; ++nf)
#pragma unroll
            for (int q = 0; q < 4; ++q) acc[mf][nf][q] = 0.f;

    const int g2 = lane >> 3, rr = lane & 7;
    const int nA[3] = {3, 2, 1};

    for (int c = 0; c < kChunks; ++c) {
        if (c < kChunks - 1)
            asm volatile("cp.async.wait_group 1;" ::: "memory");
        else
            asm volatile("cp.async.wait_group 0;" ::: "memory");
        __syncthreads();

        const uint32_t Ts = sbase + kHdr + (uint32_t)(c & 1) * kStage;
        const uint32_t Bs = Ts + 3 * kAterm;

#pragma unroll
        for (int ks = 0; ks < 2; ++ks) {
            // A fragments: 3 terms x 2 m-frags
            uint32_t a[3][2][4];
            const uint32_t arow = (uint32_t)(mw * 32 + (g2 & 1) * 8 + rr);
            const uint32_t koA  = (uint32_t)(ks * 32 + (g2 >> 1) * 16);
#pragma unroll
            for (int t = 0; t < 3; ++t)
#pragma unroll
                for (int mf = 0; mf < 2; ++mf)
                    ldsm4(a[t][mf],
                          Ts + t * kAterm + (arow + mf * 16) * kRowB + koA);

            const uint32_t brow = (uint32_t)(nw * 80 + (g2 >> 1) * 8 + rr);
            const uint32_t koB  = (uint32_t)(ks * 32 + (g2 & 1) * 16);
#pragma unroll
            for (int bt = 0; bt < 3; ++bt) {
                uint32_t b[5][4];
#pragma unroll
                for (int j = 0; j < 5; ++j)
                    ldsm4(b[j], Bs + bt * kBterm + (brow + j * 16) * kRowB + koB);
#pragma unroll
                for (int at = 0; at < 3; ++at) {
                    if (at >= nA[bt]) break;
#pragma unroll
                    for (int mf = 0; mf < 2; ++mf)
#pragma unroll
                        for (int nf = 0; nf < 10; ++nf)
                            mma16816(acc[mf][nf], a[at][mf],
                                     b[nf >> 1][(nf & 1) * 2],
                                     b[nf >> 1][(nf & 1) * 2 + 1]);
                }
            }
        }
        __syncthreads();
        if (c + 2 < kChunks)
            load_chunk(c + 2, sbase + kHdr + (uint32_t)(c & 1) * kStage, m0, g, tid);
    }

    // ---- fused bias + argmax ----
#pragma unroll
    for (int mf = 0; mf < 2; ++mf) {
#pragma unroll
        for (int hi = 0; hi < 2; ++hi) {
            float bv = -3.4e38f;
            int bi = 0;
#pragma unroll
            for (int nf = 0; nf < 10; ++nf) {
#pragma unroll
                for (int cc = 0; cc < 2; ++cc) {
                    int col = nw * 80 + nf * 8 + tig * 2 + cc;
                    float v = acc[mf][nf][hi * 2 + cc] + bias_s[col];
                    if (v > bv) { bv = v; bi = col; }
                }
            }
            // reduce across the 4 lanes sharing this row
#pragma unroll
            for (int d = 1; d < 4; d <<= 1) {
                float ov = __shfl_xor_sync(0xFFFFFFFFu, bv, d);
                int   oi = __shfl_xor_sync(0xFFFFFFFFu, bi, d);
                if (ov > bv || (ov == bv && oi < bi)) { bv = ov; bi = oi; }
            }
            if (tig == 0) {
                int row = mw * 32 + mf * 16 + hi * 8 + gID;
                red_val[row * 4 + nw] = bv;
                red_idx[row * 4 + nw] = bi;
            }
        }
    }
    __syncthreads();

    if (tid < kMT) {
        float bv = -3.4e38f;
        int bi = 0x7fffffff;
#pragma unroll
        for (int w = 0; w < 4; ++w) {
            float v = red_val[tid * 4 + w];
            int   i = red_idx[tid * 4 + w];
            if (v > bv || (v == bv && i < bi)) { bv = v; bi = i; }
        }
        idx_s[tid] = bi;
        atomicAdd(&g_counts[g * kV + bi], 1);
    }
    __syncthreads();

    // ---- coalesced codevector gather ----
    const float4* cbv  = (const float4*)cb;
    float4*       outv = (float4*)out;
    for (int e = tid; e < kMT * 32; e += 256) {
        int m = e >> 5, j = e & 31;
        int vi = idx_s[m];
        outv[(size_t)(m0 + m) * 64 + g * 32 + j] =
            cbv[(size_t)(g * kV + vi) * 32 + j];
    }
}

// ---------------- tiny kernels ----------------
__global__ void vq_zero() {
    if (threadIdx.x < kGV) g_counts[threadIdx.x] = 0;
}

__global__ void vq_ppl(float* __restrict__ out, int out_size) {
    __shared__ float terms[kGV];
    int t = threadIdx.x;               // 320 threads
    for (int g = 0; g < kG; g++) {
        float m = (float)g_counts[g * kV + t] / (float)kBT;
        terms[g * kV + t] = m * logf(m + 1e-7f);
    }
    __syncthreads();
    if (t == 0) {
        float p = 0.f;
        for (int g = 0; g < kG; g++) {
            float s = 0.f;
            for (int v = 0; v < kV; v++) s += terms[g * kV + v];
            p += expf(-s);
        }
        out[out_size - 1] = p;
    }
}

extern "C" void kernel_launch(void* const* d_in, const int* in_sizes, int n_in,
                              void* d_out, int out_size) {
    (void)in_sizes; (void)n_in;
    const float* hid  = (const float*)d_in[0];
    const float* W    = (const float*)d_in[1];
    const float* bias = (const float*)d_in[2];
    const float* cb   = (const float*)d_in[3];
    float* out = (float*)d_out;

    cudaFuncSetAttribute(vq_mma, cudaFuncAttributeMaxDynamicSharedMemorySize,
                         kSmemBytes);

    vq_zero<<<1, kGV>>>();
    split_h_kernel<<<(kBT * kH / 4) / 256, 256>>>(hid);
    split_w_kernel<<<(kH * kGV) / 256, 256>>>(W);
    vq_mma<<<(kBT / kMT) * kG, 256, kSmemBytes>>>(bias, cb, out);
    vq_ppl<<<1, kV>>>(out, out_size);
}

// round 5
// speedup vs baseline: 2.9340x; 1.1084x over previous
#include <cuda_runtime.h>
#include <cuda_bf16.h>
#include <cstdint>

// ---------------------------------------------------------------------------
// Wav2Vec2 Gumbel VQ via mma.sync bf16 (sm_100 baseline path).
//   logits = h @ W + b with bf16x3 split, 6 products (fp32-quality).
//   2 CTAs/SM (half-group N-tiles) -> partial argmax -> merge kernel.
// ---------------------------------------------------------------------------

namespace {
constexpr int kBT = 65536;
constexpr int kH  = 512;
constexpr int kV  = 320;
constexpr int kG  = 2;
constexpr int kGV = kG * kV;

constexpr int kMT = 64;                   // tokens per CTA
constexpr int kNT = 160;                  // logit cols per CTA (half group)
constexpr int kKC = 32;                   // K per chunk (2 mma k-steps)
constexpr int kChunks = kH / kKC;         // 16

constexpr uint32_t kRowB   = 80;                           // 32 bf16 + pad
constexpr uint32_t kAterm  = kMT * kRowB;                  // 5120
constexpr uint32_t kBterm  = kNT * kRowB;                  // 12800
constexpr uint32_t kStage  = 3 * kAterm + 3 * kBterm;      // 53760
constexpr uint32_t kHdr    = 4096;
constexpr uint32_t kSmemBytes = kHdr + 2 * kStage;         // 111616
}  // namespace

// global scratch (no cudaMalloc allowed)
__device__ __align__(256) __nv_bfloat16 g_h1[(size_t)kBT * kH];
__device__ __align__(256) __nv_bfloat16 g_h2[(size_t)kBT * kH];
__device__ __align__(256) __nv_bfloat16 g_h3[(size_t)kBT * kH];
__device__ __align__(256) __nv_bfloat16 g_w1t[kGV * kH];
__device__ __align__(256) __nv_bfloat16 g_w2t[kGV * kH];
__device__ __align__(256) __nv_bfloat16 g_w3t[kGV * kH];
__device__ float g_pval[4 * kBT];   // [(g*2+half)][token]
__device__ int   g_pidx[4 * kBT];
__device__ int   g_counts[kGV];

// ---------------- PTX helpers ----------------
__device__ __forceinline__ uint32_t smem_u32(const void* p) {
    uint32_t a;
    asm("{ .reg .u64 t; cvta.to.shared.u64 t, %1; cvt.u32.u64 %0, t; }"
        : "=r"(a) : "l"(p));
    return a;
}
__device__ __forceinline__ void cpa16(uint32_t s, const void* g) {
    asm volatile("cp.async.cg.shared.global [%0], [%1], 16;" :: "r"(s), "l"(g));
}
__device__ __forceinline__ void cpa_commit() {
    asm volatile("cp.async.commit_group;" ::: "memory");
}
__device__ __forceinline__ void ldsm4(uint32_t* d, uint32_t addr) {
    asm volatile("ldmatrix.sync.aligned.m8n8.x4.shared.b16 {%0,%1,%2,%3}, [%4];"
                 : "=r"(d[0]), "=r"(d[1]), "=r"(d[2]), "=r"(d[3]) : "r"(addr));
}
__device__ __forceinline__ void mma16816(float* c, const uint32_t* a,
                                         uint32_t b0, uint32_t b1) {
    asm volatile(
        "mma.sync.aligned.m16n8k16.row.col.f32.bf16.bf16.f32 "
        "{%0,%1,%2,%3}, {%4,%5,%6,%7}, {%8,%9}, {%0,%1,%2,%3};"
        : "+f"(c[0]), "+f"(c[1]), "+f"(c[2]), "+f"(c[3])
        : "r"(a[0]), "r"(a[1]), "r"(a[2]), "r"(a[3]), "r"(b0), "r"(b1));
}

// ---------------- split kernels ----------------
__device__ __forceinline__ uint32_t pk2(__nv_bfloat16 x, __nv_bfloat16 y) {
    return (uint32_t)__bfloat16_as_ushort(x) |
           ((uint32_t)__bfloat16_as_ushort(y) << 16);
}

__global__ void __launch_bounds__(256) split_h_kernel(const float* __restrict__ h) {
    size_t i = (size_t)blockIdx.x * 256 + threadIdx.x;   // one float4 each
    float4 x = ((const float4*)h)[i];
    float v[4] = {x.x, x.y, x.z, x.w};
    __nv_bfloat16 a[4], b[4], c[4];
#pragma unroll
    for (int j = 0; j < 4; j++) {
        a[j] = __float2bfloat16_rn(v[j]);
        float r = v[j] - __bfloat162float(a[j]);
        b[j] = __float2bfloat16_rn(r);
        float r2 = r - __bfloat162float(b[j]);
        c[j] = __float2bfloat16_rn(r2);
    }
    ((uint2*)g_h1)[i] = make_uint2(pk2(a[0], a[1]), pk2(a[2], a[3]));
    ((uint2*)g_h2)[i] = make_uint2(pk2(b[0], b[1]), pk2(b[2], b[3]));
    ((uint2*)g_h3)[i] = make_uint2(pk2(c[0], c[1]), pk2(c[2], c[3]));
}

__global__ void __launch_bounds__(256) split_w_kernel(const float* __restrict__ W) {
    int idx = blockIdx.x * 256 + threadIdx.x;   // over 512*640
    int k = idx / kGV;
    int n = idx - k * kGV;
    float v = W[idx];
    __nv_bfloat16 a = __float2bfloat16_rn(v);
    float r = v - __bfloat162float(a);
    __nv_bfloat16 b = __float2bfloat16_rn(r);
    float r2 = r - __bfloat162float(b);
    __nv_bfloat16 c = __float2bfloat16_rn(r2);
    size_t o = (size_t)n * kH + k;               // transposed [n][k]
    g_w1t[o] = a; g_w2t[o] = b; g_w3t[o] = c;
}

// ---------------- main tensor kernel ----------------
__device__ __forceinline__ void load_chunk(int c, uint32_t Ts, int m0,
                                           int nbase, int tid) {
    // A: 3 terms x 64 rows x 4 x 16B = 768 cp.async (3 per thread)
#pragma unroll
    for (int t = 0; t < 3; ++t) {
        int row = tid >> 2, cs = tid & 3;
        const __nv_bfloat16* hp = (t == 0) ? g_h1 : (t == 1) ? g_h2 : g_h3;
        const void* gp = hp + ((size_t)(m0 + row) * kH + c * kKC + cs * 8);
        cpa16(Ts + t * kAterm + row * kRowB + cs * 16, gp);
    }
    // B: 3 terms x 160 rows x 4 x 16B = 1920 cp.async
    const uint32_t B0 = Ts + 3 * kAterm;
#pragma unroll
    for (int i = 0; i < 8; ++i) {
        int gi = tid + i * 256;
        if (gi < 1920) {
            int t = gi / 640;
            int e = gi - t * 640;
            int n = e >> 2, cs = e & 3;
            const __nv_bfloat16* wp = (t == 0) ? g_w1t : (t == 1) ? g_w2t : g_w3t;
            const void* gp = wp + ((size_t)(nbase + n) * kH + c * kKC + cs * 8);
            cpa16(B0 + t * kBterm + n * kRowB + cs * 16, gp);
        }
    }
    cpa_commit();
}

__global__ void __launch_bounds__(256, 2)
vq_mma(const float* __restrict__ bias)
{
    extern __shared__ __align__(1024) char smem_raw[];
    const uint32_t sbase = smem_u32(smem_raw);
    float* red_val = (float*)smem_raw;                 // [64][2]
    int*   red_idx = (int*)(smem_raw + 512);           // [64][2]
    float* bias_s  = (float*)(smem_raw + 1024);        // [160]

    const int tid  = threadIdx.x;
    const int warp = tid >> 5;
    const int lane = tid & 31;
    const int mw   = warp >> 1;            // 0..3 (16 rows each)
    const int nw   = warp & 1;             // 0..1 (80 cols each)
    const int gID  = lane >> 2;
    const int tig  = lane & 3;
    const int bx   = blockIdx.x;
    const int half = bx & 1;
    const int g    = (bx >> 1) & 1;
    const int m0   = (bx >> 2) * kMT;
    const int nbase = g * kV + half * kNT;             // B row base

    for (int i = tid; i < kNT; i += 256) bias_s[i] = bias[nbase + i];

    load_chunk(0, sbase + kHdr, m0, nbase, tid);
    load_chunk(1, sbase + kHdr + kStage, m0, nbase, tid);

    float acc[10][4];
#pragma unroll
    for (int nf = 0; nf < 10; ++nf)
#pragma unroll
        for (int q = 0; q < 4; ++q) acc[nf][q] = 0.f;

    const int g2 = lane >> 3, rr = lane & 7;
    const int nA[3] = {3, 2, 1};

    for (int c = 0; c < kChunks; ++c) {
        if (c < kChunks - 1)
            asm volatile("cp.async.wait_group 1;" ::: "memory");
        else
            asm volatile("cp.async.wait_group 0;" ::: "memory");
        __syncthreads();

        const uint32_t Ts = sbase + kHdr + (uint32_t)(c & 1) * kStage;
        const uint32_t Bs = Ts + 3 * kAterm;

#pragma unroll
        for (int ks = 0; ks < 2; ++ks) {
            // A fragments: 3 terms, 1 m-frag (warp rows = 16)
            uint32_t a[3][4];
            const uint32_t arow = (uint32_t)(mw * 16 + (g2 & 1) * 8 + rr);
            const uint32_t koA  = (uint32_t)(ks * 32 + (g2 >> 1) * 16);
#pragma unroll
            for (int t = 0; t < 3; ++t)
                ldsm4(a[t], Ts + t * kAterm + arow * kRowB + koA);

            const uint32_t brow = (uint32_t)(nw * 80 + (g2 >> 1) * 8 + rr);
            const uint32_t koB  = (uint32_t)(ks * 32 + (g2 & 1) * 16);
#pragma unroll
            for (int bt = 0; bt < 3; ++bt) {
                uint32_t b[5][4];
#pragma unroll
                for (int j = 0; j < 5; ++j)
                    ldsm4(b[j], Bs + bt * kBterm + (brow + j * 16) * kRowB + koB);
#pragma unroll
                for (int at = 0; at < 3; ++at) {
                    if (at >= nA[bt]) break;
#pragma unroll
                    for (int nf = 0; nf < 10; ++nf)
                        mma16816(acc[nf], a[at],
                                 b[nf >> 1][(nf & 1) * 2],
                                 b[nf >> 1][(nf & 1) * 2 + 1]);
                }
            }
        }
        __syncthreads();
        if (c + 2 < kChunks)
            load_chunk(c + 2, sbase + kHdr + (uint32_t)(c & 1) * kStage,
                       m0, nbase, tid);
    }

    // ---- fused bias + local argmax over this CTA's 160 cols ----
#pragma unroll
    for (int hi = 0; hi < 2; ++hi) {
        float bv = -3.4e38f;
        int bi = 0;
#pragma unroll
        for (int nf = 0; nf < 10; ++nf) {
#pragma unroll
            for (int cc = 0; cc < 2; ++cc) {
                int col = nw * 80 + nf * 8 + tig * 2 + cc;
                float v = acc[nf][hi * 2 + cc] + bias_s[col];
                if (v > bv) { bv = v; bi = col; }
            }
        }
#pragma unroll
        for (int d = 1; d < 4; d <<= 1) {
            float ov = __shfl_xor_sync(0xFFFFFFFFu, bv, d);
            int   oi = __shfl_xor_sync(0xFFFFFFFFu, bi, d);
            if (ov > bv || (ov == bv && oi < bi)) { bv = ov; bi = oi; }
        }
        if (tig == 0) {
            int row = mw * 16 + hi * 8 + gID;
            red_val[row * 2 + nw] = bv;
            red_idx[row * 2 + nw] = bi;
        }
    }
    __syncthreads();

    if (tid < kMT) {
        float v0 = red_val[tid * 2], v1 = red_val[tid * 2 + 1];
        int   i0 = red_idx[tid * 2], i1 = red_idx[tid * 2 + 1];
        float bv = v0; int bi = i0;
        if (v1 > bv || (v1 == bv && i1 < bi)) { bv = v1; bi = i1; }
        int slot = (g * 2 + half) * kBT + m0 + tid;
        g_pval[slot] = bv;
        g_pidx[slot] = half * kNT + bi;     // group-local index 0..319
    }
}

// ---------------- merge + gather kernel ----------------
__global__ void __launch_bounds__(256)
vq_finish(const float* __restrict__ cb,    // [640][128]
          float* __restrict__ out)         // [BT][256]
{
    __shared__ int idx_s[kMT * 2];
    const int tid = threadIdx.x;
    const int m0  = blockIdx.x * kMT;

    if (tid < 128) {
        int m = tid >> 1, g = tid & 1;
        int tok = m0 + m;
        float v0 = g_pval[(g * 2 + 0) * kBT + tok];
        float v1 = g_pval[(g * 2 + 1) * kBT + tok];
        int   i0 = g_pidx[(g * 2 + 0) * kBT + tok];
        int   i1 = g_pidx[(g * 2 + 1) * kBT + tok];
        int bi = (v1 > v0) ? i1 : i0;       // tie -> half0 (lower idx)
        idx_s[m * 2 + g] = bi;
        atomicAdd(&g_counts[g * kV + bi], 1);
    }
    __syncthreads();

    const float4* cbv  = (const float4*)cb;
    float4*       outv = (float4*)out;
#pragma unroll
    for (int i = 0; i < 16; ++i) {
        int e = tid + i * 256;              // 0..4095
        int m = e >> 6, q = e & 63;
        int g = q >> 5, j = q & 31;
        int vi = idx_s[m * 2 + g];
        outv[(size_t)(m0 + m) * 64 + q] =
            cbv[(size_t)(g * kV + vi) * 32 + j];
    }
}

// ---------------- tiny kernels ----------------
__global__ void vq_zero() {
    if (threadIdx.x < kGV) g_counts[threadIdx.x] = 0;
}

__global__ void vq_ppl(float* __restrict__ out, int out_size) {
    __shared__ float terms[kGV];
    int t = threadIdx.x;               // 320 threads
    for (int g = 0; g < kG; g++) {
        float m = (float)g_counts[g * kV + t] / (float)kBT;
        terms[g * kV + t] = m * logf(m + 1e-7f);
    }
    __syncthreads();
    if (t == 0) {
        float p = 0.f;
        for (int g = 0; g < kG; g++) {
            float s = 0.f;
            for (int v = 0; v < kV; v++) s += terms[g * kV + v];
            p += expf(-s);
        }
        out[out_size - 1] = p;
    }
}

extern "C" void kernel_launch(void* const* d_in, const int* in_sizes, int n_in,
                              void* d_out, int out_size) {
    (void)in_sizes; (void)n_in;
    const float* hid  = (const float*)d_in[0];
    const float* W    = (const float*)d_in[1];
    const float* bias = (const float*)d_in[2];
    const float* cb   = (const float*)d_in[3];
    float* out = (float*)d_out;

    cudaFuncSetAttribute(vq_mma, cudaFuncAttributeMaxDynamicSharedMemorySize,
                         kSmemBytes);

    vq_zero<<<1, kGV>>>();
    split_h_kernel<<<(kBT * kH / 4) / 256, 256>>>(hid);
    split_w_kernel<<<(kH * kGV) / 256, 256>>>(W);
    vq_mma<<<(kBT / kMT) * 4, 256, kSmemBytes>>>(bias);
    vq_finish<<<kBT / kMT, 256>>>(cb, out);
    vq_ppl<<<1, kV>>>(out, out_size);
}